// round 13
// baseline (speedup 1.0000x reference)
#include <cuda_runtime.h>
#include <cuda_bf16.h>

// Problem constants (fixed shapes from the reference):
//   x: (B=8, C=3, H=1024, W=1024) fp32, GRID 8x8 -> tile 128x128, no padding
//   NUM_BINS=256, CLIP_LIMIT=40 -> max_val = 40*16384//256 = 2560
//   pixels per tile = 16384, T = 8*3*8*8 = 1536 tiles

#define IMG     1048576           // 1024*1024
#define NTILES  1536              // 8*3*8*8
#define NQUADS  (NTILES * 4)      // 6144 64x64 quadrants
#define NWORK   (NTILES + NQUADS) // 7680 work items
#define PIXELS  16384             // 128*128
#define MAXVAL  2560              // clip limit in counts
#define NIMG    24                // B*C
#define GRID_P  1216              // 152 SMs x 8 CTAs (extras exit via ticket)

// Per-tile LUT, integer values 0..255. 1536*256*4 = 1.5 MB (static scratch).
__device__ int g_lut[NTILES * 256];
// Quantized index image idx = clip(rz(x*255), 0, 255), packed u8. 24 MB static.
__device__ unsigned int g_idx[NIMG * IMG / 4];
// Work-stealing state (reset every launch by clahe_init).
__device__ unsigned int g_ticket;
__device__ unsigned int g_done[NIMG];   // completed hist tiles per image

// Final scale: S is in units of (1/127)*(1/127)*LUT, output = blend/255.
#define OUT_SCALE (1.0f / (127.0f * 127.0f * 255.0f))

// ---------------------------------------------------------------------------
__global__ void clahe_init() {
    if (threadIdx.x == 0) g_ticket = 0u;
    if (threadIdx.x < NIMG) g_done[threadIdx.x] = 0u;
}

// ---------------------------------------------------------------------------
// Hist item: per-tile histogram -> clip -> redistribute -> cumsum -> LUT,
// plus the packed u8 index image. Signals per-image done counter at the end.
// ---------------------------------------------------------------------------
__device__ __forceinline__ void do_hist(const float* __restrict__ x, int t,
                                        unsigned int (*h)[256],
                                        int* red, int* sc, int* s_total) {
    const int tid  = threadIdx.x;
    const int warp = tid >> 5;

    #pragma unroll
    for (int w = 0; w < 8; ++w) h[w][tid] = 0u;
    __syncthreads();

    const int tx = t & 7;
    const int ty = (t >> 3) & 7;
    const int bc = t >> 6;

    const size_t eoff = (size_t)bc * IMG + (size_t)(ty * 128) * 1024 + tx * 128;
    const float* base = x + eoff;
    unsigned int* idxb = g_idx + (eoff >> 2);   // u32 view, 4 px each

    // 16384 pixels = 4096 float4; 256 threads x 16 iterations
    #pragma unroll 4
    for (int i = 0; i < 16; ++i) {
        const int lin = tid + i * 256;   // 0..4095
        const int row = lin >> 5;        // 32 float4 per 128-wide row
        const int c4  = lin & 31;
        const float4 v = *reinterpret_cast<const float4*>(base + row * 1024 + c4 * 4);

        // hist bins use *256 (x >= 0 so no low clamp needed)
        int b0 = min(__float2int_rz(v.x * 256.0f), 255);
        int b1 = min(__float2int_rz(v.y * 256.0f), 255);
        int b2 = min(__float2int_rz(v.z * 256.0f), 255);
        int b3 = min(__float2int_rz(v.w * 256.0f), 255);
        atomicAdd(&h[warp][b0], 1u);
        atomicAdd(&h[warp][b1], 1u);
        atomicAdd(&h[warp][b2], 1u);
        atomicAdd(&h[warp][b3], 1u);

        // index image uses *255 (reference: clip((x*255).astype(int32),0,255))
        unsigned i0 = (unsigned)min(__float2int_rz(v.x * 255.0f), 255);
        unsigned i1 = (unsigned)min(__float2int_rz(v.y * 255.0f), 255);
        unsigned i2 = (unsigned)min(__float2int_rz(v.z * 255.0f), 255);
        unsigned i3 = (unsigned)min(__float2int_rz(v.w * 255.0f), 255);
        idxb[row * 256 + c4] = i0 | (i1 << 8) | (i2 << 16) | (i3 << 24);
    }
    __syncthreads();

    // Reduce sub-histograms; each thread owns one bin
    unsigned int cnt = 0;
    #pragma unroll
    for (int w = 0; w < 8; ++w) cnt += h[w][tid];

    // Clip
    const int hc = min((int)cnt, MAXVAL);

    // Block reduction: total clipped mass
    red[tid] = hc;
    __syncthreads();
    #pragma unroll
    for (int off = 128; off > 0; off >>= 1) {
        if (tid < off) red[tid] += red[tid + off];
        __syncthreads();
    }
    if (tid == 0) *s_total = red[0];
    __syncthreads();

    // Redistribute excess (integer-exact, matching the fp32-exact reference math)
    const int clipped  = PIXELS - *s_total;
    const int residual = clipped & 255;          // mod 256 (clipped >= 0)
    const int add      = (clipped - residual) >> 8;
    const int hf       = hc + add + ((tid < residual) ? 1 : 0);

    // Inclusive Hillis-Steele scan over 256 bins
    sc[tid] = hf;
    __syncthreads();
    #pragma unroll
    for (int off = 1; off < 256; off <<= 1) {
        const int u = (tid >= off) ? sc[tid - off] : 0;
        __syncthreads();
        sc[tid] += u;
        __syncthreads();
    }

    // LUT: floor(clip(cumsum * 255/16384, 0, 255)); 255/16384 exact in binary
    const float cum = (float)sc[tid];
    const float lv  = floorf(fminf(cum * (255.0f / 16384.0f), 255.0f));
    g_lut[t * 256 + tid] = (int)lv;     // exact integer 0..255

    // Release: make this tile's LUT + idx visible, then bump the image counter
    __syncthreads();
    if (tid == 0) {
        __threadfence();
        atomicAdd(&g_done[bc], 1u);
    }
}

// ---------------------------------------------------------------------------
// Apply item: one 64x64 quadrant, integer SIMD bilinear LUT blend.
// Spins (thread 0 + nanosleep) until the image's 64 tile LUTs are published.
// ---------------------------------------------------------------------------
__device__ __forceinline__ void do_apply(float* __restrict__ out, int q,
                                         unsigned int* packed) {
    const int tid = threadIdx.x;
    const int qx  = q & 15;
    const int qy  = (q >> 4) & 15;
    const int bc  = q >> 8;

    // Wait for this image's LUTs (hist tickets precede apply tickets, so
    // progress is guaranteed; nanosleep keeps the spin off the issue path).
    if (tid == 0) {
        while (atomicAdd(&g_done[bc], 0u) < 64u) __nanosleep(128);
        __threadfence();
    }
    __syncthreads();

    // Tile-pair indices for this quadrant (j == qy / qx in the reference)
    const int r0 = (qy == 0) ? 0 : min((qy - 1) >> 1, 7);
    const int r1 = min(r0 + 1, 7);
    const int c0 = (qx == 0) ? 0 : min((qx - 1) >> 1, 7);
    const int c1 = min(c0 + 1, 7);

    // Pack the 4 LUTs (integers 0..255) into bytes A,B,C,D
    {
        const int lb = bc * 64;
        const unsigned A = (unsigned)g_lut[(lb + r0 * 8 + c0) * 256 + tid];
        const unsigned B = (unsigned)g_lut[(lb + r0 * 8 + c1) * 256 + tid];
        const unsigned C = (unsigned)g_lut[(lb + r1 * 8 + c0) * 256 + tid];
        const unsigned D = (unsigned)g_lut[(lb + r1 * 8 + c1) * 256 + tid];
        packed[tid] = A | (B << 8) | (C << 16) | (D << 24);
    }
    __syncthreads();

    // Integer weight generators: w*127 = base - p*step  (p = coord in quadrant)
    const int stepy = (qy == 0) ? 0 : 1;
    const int basey = (qy == 0) ? 127 : ((qy & 1) ? 127 : 63);
    const int stepx = (qx == 0) ? 0 : 1;
    const int basex = (qx == 0) ? 127 : ((qx & 1) ? 127 : 63);

    const size_t boff = (size_t)bc * IMG + (size_t)(qy * 64) * 1024 + qx * 64;
    const unsigned int* inb = g_idx + (boff >> 2);   // u32 view, 4 px each
    float* outb = out + boff;

    // 64x64 quadrant = 1024 u32 / float4; 256 threads x 4 iterations
    #pragma unroll
    for (int i = 0; i < 4; ++i) {
        const int lin = tid + i * 256;
        const int row = lin >> 4;        // 16 u32 per 64-wide row
        const int c4  = lin & 15;
        const unsigned int pix = inb[row * 256 + c4];

        const int wyn  = basey - row * stepy;           // 0..127
        const unsigned wyb = (unsigned)(wyn | ((127 - wyn) << 8));
        const int pxb  = c4 * 4;

        float4 o;
        #pragma unroll
        for (int k = 0; k < 4; ++k) {
            const unsigned idx = (pix >> (8 * k)) & 255u;
            const unsigned u   = packed[idx];
            const unsigned uLO = __byte_perm(u, 0, 0x4240); // (A, C) as u16x2
            const unsigned uHI = __byte_perm(u, 0, 0x4341); // (B, D) as u16x2
            const int wxn  = basex - (pxb + k) * stepx;     // 0..127
            const unsigned v = (unsigned)wxn * uLO + (unsigned)(127 - wxn) * uHI;
            const int S = __dp2a_lo((int)v, (int)wyb, 0);   // wyn*lo + wynp*hi
            ((float*)&o)[k] = (float)S * OUT_SCALE;
        }
        // Streaming store: out is write-once, keep L2 for g_idx / LUTs
        __stcs(reinterpret_cast<float4*>(outb + row * 1024 + c4 * 4), o);
    }
}

// ---------------------------------------------------------------------------
// Persistent fused kernel: global ticket queue. Tickets [0,1536) = hist tiles
// (ascending image), [1536,7680) = apply quadrants (ascending image). Hist
// items never block, so apply spins always make progress -> deadlock-free.
// ATOMS-bound hist overlaps DRAM/LDS-bound apply across the whole chip.
// ---------------------------------------------------------------------------
__global__ __launch_bounds__(256) void clahe_fused(const float* __restrict__ x,
                                                   float* __restrict__ out) {
    __shared__ unsigned int h[8][256];   // hist sub-histograms / apply packed LUT
    __shared__ int red[256];
    __shared__ int sc[256];
    __shared__ int s_total;
    __shared__ unsigned int s_item;

    for (;;) {
        if (threadIdx.x == 0) s_item = atomicAdd(&g_ticket, 1u);
        __syncthreads();
        const unsigned int item = s_item;
        if (item >= NWORK) return;

        if (item < NTILES) do_hist(x, (int)item, h, red, sc, &s_total);
        else               do_apply(out, (int)(item - NTILES), h[0]);

        __syncthreads();   // protect smem (and s_item) before next iteration
    }
}

// ---------------------------------------------------------------------------
extern "C" void kernel_launch(void* const* d_in, const int* in_sizes, int n_in,
                              void* d_out, int out_size) {
    const float* x   = (const float*)d_in[0];
    float*       out = (float*)d_out;
    (void)in_sizes; (void)n_in; (void)out_size;

    clahe_init<<<1, 32>>>();
    clahe_fused<<<GRID_P, 256>>>(x, out);
}